// round 13
// baseline (speedup 1.0000x reference)
#include <cuda_runtime.h>
#include <cuda_fp16.h>
#include <cstdint>

// Cheb_conv as one batched fp16 GEMM on mma.sync (HMMA):
//   out[b,om,t] = sum_cn W[om,cn] * X[b,cn,t]
//   om=o*24+m (768), cn=c*24+n (768), t=512, b=64.
//   W[om,cn] = (Th0-Th2)[c,o](n==m) + Th1[c,o]L[n,m] + 2Th2[c,o]L2[n,m]
// R12: R10 gemm unchanged (102us, HMMA equilibrium). Non-gemm 43us attacked:
// prep1 (15us serial, grid=1) deleted — L/L2 recomputed per prepW block;
// prepW + xconv merged into ONE kernel (prepW compute hides under xconv
// streaming; one launch gap instead of three).

#define NVERT 24
#define NCH 32
#define NT 512
#define NB 64
#define CN 768
#define OM 768
#define KCH 64          // K chunk (halves) = 128B rows
#define NKCH (CN / KCH) // 12

#define NPREPW_BLK ((OM * CN) / 256)              // 2304
#define NXCONV_BLK ((NT / 128) * (CN / 32) * NB)  // 4*24*64 = 6144

__device__ __align__(16) __half g_W[OM * CN];                  // row-major [om][cn]
__device__ __align__(16) __half g_Xt[(size_t)NB * NT * CN];    // [b][t][cn]

__device__ __forceinline__ uint32_t smem_u32(const void* p) {
    uint32_t a;
    asm("{ .reg .u64 t; cvta.to.shared.u64 t, %1; cvt.u32.u64 %0, t; }" : "=r"(a) : "l"(p));
    return a;
}
#define CP_ASYNC16(dst, src) \
    asm volatile("cp.async.cg.shared.global [%0], [%1], 16;" :: "r"(dst), "l"(src) : "memory")
#define CP_COMMIT() asm volatile("cp.async.commit_group;" ::: "memory")
#define CP_WAIT1()  asm volatile("cp.async.wait_group 1;" ::: "memory")
#define CP_WAIT0()  asm volatile("cp.async.wait_group 0;" ::: "memory")
#define LDSM_X4(r0, r1, r2, r3, a) \
    asm volatile("ldmatrix.sync.aligned.m8n8.x4.shared.b16 {%0,%1,%2,%3}, [%4];" \
                 : "=r"(r0), "=r"(r1), "=r"(r2), "=r"(r3) : "r"(a))
#define MMA16816(c, a, b0, b1) \
    asm volatile("mma.sync.aligned.m16n8k16.row.col.f32.f16.f16.f32 " \
                 "{%0,%1,%2,%3}, {%4,%5,%6,%7}, {%8,%9}, {%0,%1,%2,%3};" \
                 : "+f"((c)[0]), "+f"((c)[1]), "+f"((c)[2]), "+f"((c)[3]) \
                 : "r"((a)[0]), "r"((a)[1]), "r"((a)[2]), "r"((a)[3]), "r"(b0), "r"(b1))

// ---------------- combined prep: prepW blocks + xconv blocks ----------------
__global__ void __launch_bounds__(256) cheb_prep_all(const float* __restrict__ x,
                                                     const float* __restrict__ adj,
                                                     const float* __restrict__ Theta) {
    __shared__ float sbuf[32 * 132];             // xconv: s[32][132]; prepW: L|L2|dinv
    int tid = threadIdx.x;
    int bid = blockIdx.x;

    if (bid < NPREPW_BLK) {
        // ---- prepW: compute L, L2 in-block, then 256 W entries ----
        float* Ls  = sbuf;                       // [576]
        float* L2s = sbuf + 576;                 // [576]
        float* dv  = sbuf + 1152;                // [24]
        if (tid < NVERT) {
            float s = 0.f;
            #pragma unroll
            for (int j = 0; j < NVERT; j++) s += adj[tid * NVERT + j];
            dv[tid] = (s > 0.f) ? rsqrtf(s) : 0.f;
        }
        __syncthreads();
        for (int i = tid; i < NVERT * NVERT; i += 256) {
            int r = i / NVERT, cc = i % NVERT;
            Ls[i] = adj[cc * NVERT + r] * dv[r] * dv[cc];
        }
        __syncthreads();
        for (int i = tid; i < NVERT * NVERT; i += 256) {
            int r = i / NVERT, cc = i % NVERT;
            float s = 0.f;
            #pragma unroll
            for (int q = 0; q < NVERT; q++) s += Ls[r * NVERT + q] * Ls[q * NVERT + cc];
            L2s[i] = s;
        }
        __syncthreads();
        int idx = bid * 256 + tid;               // < OM*CN
        int om = idx / CN, cn = idx % CN;
        int o = om / NVERT, m = om % NVERT;
        int c = cn / NVERT, n = cn % NVERT;
        float th0 = Theta[(0 * NCH + c) * NCH + o];
        float th1 = Theta[(1 * NCH + c) * NCH + o];
        float th2 = Theta[(2 * NCH + c) * NCH + o];
        float wv = th1 * Ls[n * NVERT + m] + 2.f * th2 * L2s[n * NVERT + m];
        if (n == m) wv += th0 - th2;
        g_W[idx] = __float2half_rn(wv);
    } else {
        // ---- xconv: x[b][cn][t] f32 -> g_Xt[b][t][cn] f16 (tile 32cn x 128t) ----
        int xb = bid - NPREPW_BLK;               // 0..6143
        int tx  = xb & 3;                        // NT/128 = 4
        int cnb = (xb >> 2) % (CN / 32);         // 24
        int b   = xb / (4 * (CN / 32));          // 64
        int t0 = tx * 128, cn0 = cnb * 32;
        float (*s)[132] = (float(*)[132])sbuf;

        const float* src = x + ((size_t)b * CN + cn0) * NT + t0;
        #pragma unroll
        for (int p = 0; p < 4; p++) {
            int i = tid + 256 * p;               // 0..1023 float4 slots
            int row = i >> 5, q = i & 31;
            float4 v = *(const float4*)(src + (size_t)row * NT + q * 4);
            *(float4*)&s[row][q * 4] = v;
        }
        __syncthreads();
        __half* dst = g_Xt + ((size_t)b * NT + t0) * CN + cn0;
        #pragma unroll
        for (int p = 0; p < 2; p++) {
            int i = tid + 256 * p;               // 0..511 output float4 (8 halves)
            int t = i >> 2, h = i & 3;
            __half2 hv[4];
            #pragma unroll
            for (int q = 0; q < 4; q++)
                hv[q] = __floats2half2_rn(s[h * 8 + 2 * q][t], s[h * 8 + 2 * q + 1][t]);
            *(float4*)(dst + (size_t)t * CN + h * 8) = *(float4*)hv;
        }
    }
}

// ---------------- GEMM: CTA 128(om) x 128(t), warp 32x64, K=768 (R10, proven) ----------------
#define SM_A(s) ((s) * 16384)
#define SM_B(s) (49152 + (s) * 16384)
#define SMEM_TOTAL 98304

__device__ __forceinline__ void prefetch_tiles(uint32_t sb, int buf, int kc, int tid,
                                               const __half* Ag, const __half* Bg) {
    const __half* as = Ag + kc * KCH;
    #pragma unroll
    for (int i = 0; i < 4; i++) {
        int idx = tid + 256 * i, row = idx >> 3, ch = idx & 7;
        uint32_t d = sb + SM_A(buf) + row * 128 + ((ch ^ (row & 7)) << 4);
        CP_ASYNC16(d, as + (size_t)row * CN + ch * 8);
    }
    const __half* bs = Bg + kc * KCH;
    #pragma unroll
    for (int i = 0; i < 4; i++) {
        int idx = tid + 256 * i, row = idx >> 3, ch = idx & 7;
        uint32_t d = sb + SM_B(buf) + row * 128 + ((ch ^ (row & 7)) << 4);
        CP_ASYNC16(d, bs + (size_t)row * CN + ch * 8);
    }
    CP_COMMIT();
}

__global__ void __launch_bounds__(256, 2) cheb_gemm(float* __restrict__ out) {
    extern __shared__ __align__(16) unsigned char sm[];
    uint32_t sb = smem_u32(sm);
    int tid = threadIdx.x, lane = tid & 31, warp = tid >> 5;
    int wr = warp & 3, wc = warp >> 2;               // 4(m) x 2(n) warps
    int tt = blockIdx.x, omt = blockIdx.y, b = blockIdx.z;

    const __half* Ag = g_W + (size_t)(omt * 128) * CN;
    const __half* Bg = g_Xt + ((size_t)b * NT + tt * 128) * CN;

    float acc[2][8][4];
    #pragma unroll
    for (int mi = 0; mi < 2; mi++)
        #pragma unroll
        for (int nj = 0; nj < 8; nj++)
            #pragma unroll
            for (int q = 0; q < 4; q++) acc[mi][nj][q] = 0.f;

    prefetch_tiles(sb, 0, 0, tid, Ag, Bg);
    prefetch_tiles(sb, 1, 1, tid, Ag, Bg);

    int arow = wr * 32 + (lane & 15);                // + mi*16
    int ak   = lane >> 4;
    int brow = wc * 64 + (lane & 7) + ((lane >> 4) << 3);   // + nj*16
    int bk   = (lane >> 3) & 1;

    for (int c = 0; c < NKCH; c++) {
        if (c < NKCH - 1) CP_WAIT1(); else CP_WAIT0();
        __syncthreads();
        if (c + 2 < NKCH) prefetch_tiles(sb, (c + 2) % 3, c + 2, tid, Ag, Bg);

        uint32_t Ab = sb + SM_A(c % 3);
        uint32_t Bb = sb + SM_B(c % 3);

        #pragma unroll
        for (int ks = 0; ks < 4; ks++) {
            uint32_t a[2][4];
            #pragma unroll
            for (int mi = 0; mi < 2; mi++) {
                int row = arow + mi * 16;
                int ch = (ks * 2 + ak) ^ (row & 7);
                LDSM_X4(a[mi][0], a[mi][1], a[mi][2], a[mi][3], Ab + row * 128 + (ch << 4));
            }
            uint32_t bf[8][2];
            #pragma unroll
            for (int nj = 0; nj < 4; nj++) {
                int row = brow + nj * 16;
                int ch = (ks * 2 + bk) ^ (row & 7);
                LDSM_X4(bf[2 * nj][0], bf[2 * nj][1], bf[2 * nj + 1][0], bf[2 * nj + 1][1],
                        Bb + row * 128 + (ch << 4));
            }
            #pragma unroll
            for (int mi = 0; mi < 2; mi++)
                #pragma unroll
                for (int nj = 0; nj < 8; nj++)
                    MMA16816(acc[mi][nj], a[mi], bf[nj][0], bf[nj][1]);
        }
    }

    // epilogue: direct float2 stores
    int om0 = omt * 128 + wr * 32 + (lane >> 2);
    int t0g = tt * 128 + wc * 64 + (lane & 3) * 2;
    #pragma unroll
    for (int mi = 0; mi < 2; mi++) {
        #pragma unroll
        for (int nj = 0; nj < 8; nj++) {
            float* p0 = out + ((size_t)b * OM + om0 + mi * 16) * NT + t0g + nj * 8;
            *(float2*)p0 = make_float2(acc[mi][nj][0], acc[mi][nj][1]);
            *(float2*)(p0 + 8 * NT) = make_float2(acc[mi][nj][2], acc[mi][nj][3]);
        }
    }
}

extern "C" void kernel_launch(void* const* d_in, const int* in_sizes, int n_in,
                              void* d_out, int out_size) {
    const float* x     = (const float*)d_in[0];   // (64,32,24,512)
    const float* adj   = (const float*)d_in[1];   // (24,24)
    const float* Theta = (const float*)d_in[2];   // (3,32,32)
    float* out = (float*)d_out;                   // (64,32,24,512)

    cudaFuncSetAttribute(cheb_gemm, cudaFuncAttributeMaxDynamicSharedMemorySize, SMEM_TOTAL);

    cheb_prep_all<<<NPREPW_BLK + NXCONV_BLK, 256>>>(x, adj, Theta);
    cheb_gemm<<<dim3(NT / 128, OM / 128, NB), 256, SMEM_TOTAL>>>(out);
}

// round 14
// speedup vs baseline: 1.4875x; 1.4875x over previous
#include <cuda_runtime.h>
#include <cuda_fp16.h>
#include <cstdint>

// Cheb_conv as one batched fp16 GEMM on mma.sync (HMMA):
//   out[b,om,t] = sum_cn W[om,cn] * X[b,cn,t]
//   om=o*24+m (768), cn=c*24+n (768), t=512, b=64.
//   W[om,cn] = (Th0-Th2)[c,o](n==m) + Th1[c,o]L[n,m] + 2Th2[c,o]L2[n,m]
// R14: R10 config (best measured: 145.4us, gemm 102us) with ONE change:
// the serial grid=1 prep1 kernel (15us) is deleted; prepW recomputes
// dinv/L/L2 per block in smem. xconv + gemm byte-identical to R10.

#define NVERT 24
#define NCH 32
#define NT 512
#define NB 64
#define CN 768
#define OM 768
#define KCH 64          // K chunk (halves) = 128B rows
#define NKCH (CN / KCH) // 12

__device__ __align__(16) __half g_W[OM * CN];                  // row-major [om][cn]
__device__ __align__(16) __half g_Xt[(size_t)NB * NT * CN];    // [b][t][cn]

__device__ __forceinline__ uint32_t smem_u32(const void* p) {
    uint32_t a;
    asm("{ .reg .u64 t; cvta.to.shared.u64 t, %1; cvt.u32.u64 %0, t; }" : "=r"(a) : "l"(p));
    return a;
}
#define CP_ASYNC16(dst, src) \
    asm volatile("cp.async.cg.shared.global [%0], [%1], 16;" :: "r"(dst), "l"(src) : "memory")
#define CP_COMMIT() asm volatile("cp.async.commit_group;" ::: "memory")
#define CP_WAIT1()  asm volatile("cp.async.wait_group 1;" ::: "memory")
#define CP_WAIT0()  asm volatile("cp.async.wait_group 0;" ::: "memory")
#define LDSM_X4(r0, r1, r2, r3, a) \
    asm volatile("ldmatrix.sync.aligned.m8n8.x4.shared.b16 {%0,%1,%2,%3}, [%4];" \
                 : "=r"(r0), "=r"(r1), "=r"(r2), "=r"(r3) : "r"(a))
#define MMA16816(c, a, b0, b1) \
    asm volatile("mma.sync.aligned.m16n8k16.row.col.f32.f16.f16.f32 " \
                 "{%0,%1,%2,%3}, {%4,%5,%6,%7}, {%8,%9}, {%0,%1,%2,%3};" \
                 : "+f"((c)[0]), "+f"((c)[1]), "+f"((c)[2]), "+f"((c)[3]) \
                 : "r"((a)[0]), "r"((a)[1]), "r"((a)[2]), "r"((a)[3]), "r"(b0), "r"(b1))

// ---------------- prepW: W[om][cn] fp16; L/L2 recomputed per block ----------------
__global__ void __launch_bounds__(256) cheb_prepW(const float* __restrict__ adj,
                                                  const float* __restrict__ Theta) {
    __shared__ float Ls[NVERT * NVERT];
    __shared__ float L2s[NVERT * NVERT];
    __shared__ float dv[NVERT];
    int tid = threadIdx.x;
    if (tid < NVERT) {
        float s = 0.f;
        #pragma unroll
        for (int j = 0; j < NVERT; j++) s += adj[tid * NVERT + j];
        dv[tid] = (s > 0.f) ? rsqrtf(s) : 0.f;
    }
    __syncthreads();
    for (int i = tid; i < NVERT * NVERT; i += 256) {
        int r = i / NVERT, cc = i % NVERT;
        Ls[i] = adj[cc * NVERT + r] * dv[r] * dv[cc];
    }
    __syncthreads();
    for (int i = tid; i < NVERT * NVERT; i += 256) {
        int r = i / NVERT, cc = i % NVERT;
        float s = 0.f;
        #pragma unroll
        for (int q = 0; q < NVERT; q++) s += Ls[r * NVERT + q] * Ls[q * NVERT + cc];
        L2s[i] = s;
    }
    __syncthreads();
    int idx = blockIdx.x * 256 + tid;            // < OM*CN
    int om = idx / CN, cn = idx % CN;
    int o = om / NVERT, m = om % NVERT;
    int c = cn / NVERT, n = cn % NVERT;
    float th0 = Theta[(0 * NCH + c) * NCH + o];
    float th1 = Theta[(1 * NCH + c) * NCH + o];
    float th2 = Theta[(2 * NCH + c) * NCH + o];
    float wv = th1 * Ls[n * NVERT + m] + 2.f * th2 * L2s[n * NVERT + m];
    if (n == m) wv += th0 - th2;
    g_W[idx] = __float2half_rn(wv);
}

// ---------------- xconv: x[b][cn][t] f32 -> g_Xt[b][t][cn] f16 (R10) ----------------
__global__ void __launch_bounds__(256) cheb_xconv(const float* __restrict__ x) {
    __shared__ float s[32][132];
    int tid = threadIdx.x;
    int t0 = blockIdx.x * 128, cn0 = blockIdx.y * 32, b = blockIdx.z;
    const float* src = x + ((size_t)b * CN + cn0) * NT + t0;
    #pragma unroll
    for (int p = 0; p < 4; p++) {
        int i = tid + 256 * p;                       // 0..1023 float4 slots
        int row = i >> 5, q = i & 31;
        float4 v = *(const float4*)(src + (size_t)row * NT + q * 4);
        *(float4*)&s[row][q * 4] = v;
    }
    __syncthreads();
    __half* dst = g_Xt + ((size_t)b * NT + t0) * CN + cn0;
    #pragma unroll
    for (int p = 0; p < 2; p++) {
        int i = tid + 256 * p;                       // 0..511 output float4 (8 halves)
        int t = i >> 2, h = i & 3;
        __half2 hv[4];
        #pragma unroll
        for (int q = 0; q < 4; q++)
            hv[q] = __floats2half2_rn(s[h * 8 + 2 * q][t], s[h * 8 + 2 * q + 1][t]);
        *(float4*)(dst + (size_t)t * CN + h * 8) = *(float4*)hv;
    }
}

// ---------------- GEMM: CTA 128(om) x 128(t), warp 32x64, K=768 (R10, proven) ----------------
#define SM_A(s) ((s) * 16384)
#define SM_B(s) (49152 + (s) * 16384)
#define SMEM_TOTAL 98304

__device__ __forceinline__ void prefetch_tiles(uint32_t sb, int buf, int kc, int tid,
                                               const __half* Ag, const __half* Bg) {
    const __half* as = Ag + kc * KCH;
    #pragma unroll
    for (int i = 0; i < 4; i++) {
        int idx = tid + 256 * i, row = idx >> 3, ch = idx & 7;
        uint32_t d = sb + SM_A(buf) + row * 128 + ((ch ^ (row & 7)) << 4);
        CP_ASYNC16(d, as + (size_t)row * CN + ch * 8);
    }
    const __half* bs = Bg + kc * KCH;
    #pragma unroll
    for (int i = 0; i < 4; i++) {
        int idx = tid + 256 * i, row = idx >> 3, ch = idx & 7;
        uint32_t d = sb + SM_B(buf) + row * 128 + ((ch ^ (row & 7)) << 4);
        CP_ASYNC16(d, bs + (size_t)row * CN + ch * 8);
    }
    CP_COMMIT();
}

__global__ void __launch_bounds__(256, 2) cheb_gemm(float* __restrict__ out) {
    extern __shared__ __align__(16) unsigned char sm[];
    uint32_t sb = smem_u32(sm);
    int tid = threadIdx.x, lane = tid & 31, warp = tid >> 5;
    int wr = warp & 3, wc = warp >> 2;               // 4(m) x 2(n) warps
    int tt = blockIdx.x, omt = blockIdx.y, b = blockIdx.z;

    const __half* Ag = g_W + (size_t)(omt * 128) * CN;
    const __half* Bg = g_Xt + ((size_t)b * NT + tt * 128) * CN;

    float acc[2][8][4];
    #pragma unroll
    for (int mi = 0; mi < 2; mi++)
        #pragma unroll
        for (int nj = 0; nj < 8; nj++)
            #pragma unroll
            for (int q = 0; q < 4; q++) acc[mi][nj][q] = 0.f;

    prefetch_tiles(sb, 0, 0, tid, Ag, Bg);
    prefetch_tiles(sb, 1, 1, tid, Ag, Bg);

    int arow = wr * 32 + (lane & 15);                // + mi*16
    int ak   = lane >> 4;
    int brow = wc * 64 + (lane & 7) + ((lane >> 4) << 3);   // + nj*16
    int bk   = (lane >> 3) & 1;

    for (int c = 0; c < NKCH; c++) {
        if (c < NKCH - 1) CP_WAIT1(); else CP_WAIT0();
        __syncthreads();
        if (c + 2 < NKCH) prefetch_tiles(sb, (c + 2) % 3, c + 2, tid, Ag, Bg);

        uint32_t Ab = sb + SM_A(c % 3);
        uint32_t Bb = sb + SM_B(c % 3);

        #pragma unroll
        for (int ks = 0; ks < 4; ks++) {
            uint32_t a[2][4];
            #pragma unroll
            for (int mi = 0; mi < 2; mi++) {
                int row = arow + mi * 16;
                int ch = (ks * 2 + ak) ^ (row & 7);
                LDSM_X4(a[mi][0], a[mi][1], a[mi][2], a[mi][3], Ab + row * 128 + (ch << 4));
            }
            uint32_t bf[8][2];
            #pragma unroll
            for (int nj = 0; nj < 4; nj++) {
                int row = brow + nj * 16;
                int ch = (ks * 2 + bk) ^ (row & 7);
                LDSM_X4(bf[2 * nj][0], bf[2 * nj][1], bf[2 * nj + 1][0], bf[2 * nj + 1][1],
                        Bb + row * 128 + (ch << 4));
            }
            #pragma unroll
            for (int mi = 0; mi < 2; mi++)
                #pragma unroll
                for (int nj = 0; nj < 8; nj++)
                    MMA16816(acc[mi][nj], a[mi], bf[nj][0], bf[nj][1]);
        }
    }

    // epilogue: direct float2 stores
    int om0 = omt * 128 + wr * 32 + (lane >> 2);
    int t0g = tt * 128 + wc * 64 + (lane & 3) * 2;
    #pragma unroll
    for (int mi = 0; mi < 2; mi++) {
        #pragma unroll
        for (int nj = 0; nj < 8; nj++) {
            float* p0 = out + ((size_t)b * OM + om0 + mi * 16) * NT + t0g + nj * 8;
            *(float2*)p0 = make_float2(acc[mi][nj][0], acc[mi][nj][1]);
            *(float2*)(p0 + 8 * NT) = make_float2(acc[mi][nj][2], acc[mi][nj][3]);
        }
    }
}

extern "C" void kernel_launch(void* const* d_in, const int* in_sizes, int n_in,
                              void* d_out, int out_size) {
    const float* x     = (const float*)d_in[0];   // (64,32,24,512)
    const float* adj   = (const float*)d_in[1];   // (24,24)
    const float* Theta = (const float*)d_in[2];   // (3,32,32)
    float* out = (float*)d_out;                   // (64,32,24,512)

    cudaFuncSetAttribute(cheb_gemm, cudaFuncAttributeMaxDynamicSharedMemorySize, SMEM_TOTAL);

    cheb_prepW<<<(OM * CN) / 256, 256>>>(adj, Theta);
    cheb_xconv<<<dim3(NT / 128, CN / 32, NB), 256>>>(x);
    cheb_gemm<<<dim3(NT / 128, OM / 128, NB), 256, SMEM_TOTAL>>>(out);
}

// round 15
// speedup vs baseline: 1.6066x; 1.0801x over previous
#include <cuda_runtime.h>
#include <cuda_fp16.h>
#include <cstdint>

// Cheb_conv as one batched fp16 GEMM on mma.sync (HMMA):
//   out[b,om,t] = sum_cn W[om,cn] * X[b,cn,t]
//   om=o*24+m (768), cn=c*24+n (768), t=512, b=64.
//   W[om,cn] = (Th0-Th2)[c,o](n==m) + Th1[c,o]L[n,m] + 2Th2[c,o]L2[n,m]
// R15: prepW redundancy cut 24x (grid 2304 -> 96 blocks, 24 W entries/thread,
// uint4 stores) and merged with xconv into ONE prep launch (prepW blocks are
// 1.5% of the grid, hidden under xconv streaming). gemm identical to R10/R14.

#define NVERT 24
#define NCH 32
#define NT 512
#define NB 64
#define CN 768
#define OM 768
#define KCH 64          // K chunk (halves) = 128B rows
#define NKCH (CN / KCH) // 12

#define NPREPW_BLK 96                              // 6144 W entries per block
#define NXCONV_BLK ((NT / 128) * (CN / 32) * NB)   // 4*24*64 = 6144

__device__ __align__(16) __half g_W[OM * CN];                  // row-major [om][cn]
__device__ __align__(16) __half g_Xt[(size_t)NB * NT * CN];    // [b][t][cn]

__device__ __forceinline__ uint32_t smem_u32(const void* p) {
    uint32_t a;
    asm("{ .reg .u64 t; cvta.to.shared.u64 t, %1; cvt.u32.u64 %0, t; }" : "=r"(a) : "l"(p));
    return a;
}
#define CP_ASYNC16(dst, src) \
    asm volatile("cp.async.cg.shared.global [%0], [%1], 16;" :: "r"(dst), "l"(src) : "memory")
#define CP_COMMIT() asm volatile("cp.async.commit_group;" ::: "memory")
#define CP_WAIT1()  asm volatile("cp.async.wait_group 1;" ::: "memory")
#define CP_WAIT0()  asm volatile("cp.async.wait_group 0;" ::: "memory")
#define LDSM_X4(r0, r1, r2, r3, a) \
    asm volatile("ldmatrix.sync.aligned.m8n8.x4.shared.b16 {%0,%1,%2,%3}, [%4];" \
                 : "=r"(r0), "=r"(r1), "=r"(r2), "=r"(r3) : "r"(a))
#define MMA16816(c, a, b0, b1) \
    asm volatile("mma.sync.aligned.m16n8k16.row.col.f32.f16.f16.f32 " \
                 "{%0,%1,%2,%3}, {%4,%5,%6,%7}, {%8,%9}, {%0,%1,%2,%3};" \
                 : "+f"((c)[0]), "+f"((c)[1]), "+f"((c)[2]), "+f"((c)[3]) \
                 : "r"((a)[0]), "r"((a)[1]), "r"((a)[2]), "r"((a)[3]), "r"(b0), "r"(b1))

// ---------------- combined prep: 96 prepW blocks + 6144 xconv blocks ----------------
__global__ void __launch_bounds__(256) cheb_prep_all(const float* __restrict__ x,
                                                     const float* __restrict__ adj,
                                                     const float* __restrict__ Theta) {
    __shared__ float sbuf[32 * 132];     // xconv view [32][132]; prepW view L|L2|dv
    int tid = threadIdx.x;
    int bid = blockIdx.x;

    if (bid < NPREPW_BLK) {
        // ---- prepW: L, L2 in smem once, then 6144 W entries (24/thread) ----
        float* Ls  = sbuf;               // [576]
        float* L2s = sbuf + 576;         // [576]
        float* dv  = sbuf + 1152;        // [24]
        if (tid < NVERT) {
            float s = 0.f;
            #pragma unroll
            for (int j = 0; j < NVERT; j++) s += adj[tid * NVERT + j];
            dv[tid] = (s > 0.f) ? rsqrtf(s) : 0.f;
        }
        __syncthreads();
        for (int i = tid; i < NVERT * NVERT; i += 256) {
            int r = i / NVERT, cc = i % NVERT;
            Ls[i] = adj[cc * NVERT + r] * dv[r] * dv[cc];
        }
        __syncthreads();
        for (int i = tid; i < NVERT * NVERT; i += 256) {
            int r = i / NVERT, cc = i % NVERT;
            float s = 0.f;
            #pragma unroll
            for (int q = 0; q < NVERT; q++) s += Ls[r * NVERT + q] * Ls[q * NVERT + cc];
            L2s[i] = s;
        }
        __syncthreads();
        // 8-entry chunks: block owns chunks [bid*768, bid*768+768)
        #pragma unroll
        for (int p = 0; p < 3; p++) {
            int chunk = bid * 768 + p * 256 + tid;
            int base = chunk * 8;                    // 8-aligned, within one om row
            int om = base / CN, cn0 = base % CN;
            int o = om / NVERT, m = om % NVERT;
            __half hv[8];
            #pragma unroll
            for (int e = 0; e < 8; e++) {
                int cn = cn0 + e;
                int c = cn / NVERT, n = cn % NVERT;
                float th1 = Theta[(1 * NCH + c) * NCH + o];
                float th2 = Theta[(2 * NCH + c) * NCH + o];
                float wv = th1 * Ls[n * NVERT + m] + 2.f * th2 * L2s[n * NVERT + m];
                if (n == m) wv += Theta[(0 * NCH + c) * NCH + o] - th2;
                hv[e] = __float2half_rn(wv);
            }
            *(uint4*)&g_W[base] = *(uint4*)hv;
        }
    } else {
        // ---- xconv: x[b][cn][t] f32 -> g_Xt[b][t][cn] f16 (tile 32cn x 128t) ----
        int xb = bid - NPREPW_BLK;                   // 0..6143
        int tx  = xb & 3;                            // NT/128 = 4
        int cnb = (xb >> 2) % (CN / 32);             // 24
        int b   = xb / (4 * (CN / 32));              // 64
        int t0 = tx * 128, cn0 = cnb * 32;
        float (*s)[132] = (float(*)[132])sbuf;

        const float* src = x + ((size_t)b * CN + cn0) * NT + t0;
        #pragma unroll
        for (int p = 0; p < 4; p++) {
            int i = tid + 256 * p;                   // 0..1023 float4 slots
            int row = i >> 5, q = i & 31;
            float4 v = *(const float4*)(src + (size_t)row * NT + q * 4);
            *(float4*)&s[row][q * 4] = v;
        }
        __syncthreads();
        __half* dst = g_Xt + ((size_t)b * NT + t0) * CN + cn0;
        #pragma unroll
        for (int p = 0; p < 2; p++) {
            int i = tid + 256 * p;                   // 0..511 output float4 (8 halves)
            int t = i >> 2, h = i & 3;
            __half2 hv[4];
            #pragma unroll
            for (int q = 0; q < 4; q++)
                hv[q] = __floats2half2_rn(s[h * 8 + 2 * q][t], s[h * 8 + 2 * q + 1][t]);
            *(float4*)(dst + (size_t)t * CN + h * 8) = *(float4*)hv;
        }
    }
}

// ---------------- GEMM: CTA 128(om) x 128(t), warp 32x64, K=768 (proven) ----------------
#define SM_A(s) ((s) * 16384)
#define SM_B(s) (49152 + (s) * 16384)
#define SMEM_TOTAL 98304

__device__ __forceinline__ void prefetch_tiles(uint32_t sb, int buf, int kc, int tid,
                                               const __half* Ag, const __half* Bg) {
    const __half* as = Ag + kc * KCH;
    #pragma unroll
    for (int i = 0; i < 4; i++) {
        int idx = tid + 256 * i, row = idx >> 3, ch = idx & 7;
        uint32_t d = sb + SM_A(buf) + row * 128 + ((ch ^ (row & 7)) << 4);
        CP_ASYNC16(d, as + (size_t)row * CN + ch * 8);
    }
    const __half* bs = Bg + kc * KCH;
    #pragma unroll
    for (int i = 0; i < 4; i++) {
        int idx = tid + 256 * i, row = idx >> 3, ch = idx & 7;
        uint32_t d = sb + SM_B(buf) + row * 128 + ((ch ^ (row & 7)) << 4);
        CP_ASYNC16(d, bs + (size_t)row * CN + ch * 8);
    }
    CP_COMMIT();
}

__global__ void __launch_bounds__(256, 2) cheb_gemm(float* __restrict__ out) {
    extern __shared__ __align__(16) unsigned char sm[];
    uint32_t sb = smem_u32(sm);
    int tid = threadIdx.x, lane = tid & 31, warp = tid >> 5;
    int wr = warp & 3, wc = warp >> 2;               // 4(m) x 2(n) warps
    int tt = blockIdx.x, omt = blockIdx.y, b = blockIdx.z;

    const __half* Ag = g_W + (size_t)(omt * 128) * CN;
    const __half* Bg = g_Xt + ((size_t)b * NT + tt * 128) * CN;

    float acc[2][8][4];
    #pragma unroll
    for (int mi = 0; mi < 2; mi++)
        #pragma unroll
        for (int nj = 0; nj < 8; nj++)
            #pragma unroll
            for (int q = 0; q < 4; q++) acc[mi][nj][q] = 0.f;

    prefetch_tiles(sb, 0, 0, tid, Ag, Bg);
    prefetch_tiles(sb, 1, 1, tid, Ag, Bg);

    int arow = wr * 32 + (lane & 15);                // + mi*16
    int ak   = lane >> 4;
    int brow = wc * 64 + (lane & 7) + ((lane >> 4) << 3);   // + nj*16
    int bk   = (lane >> 3) & 1;

    for (int c = 0; c < NKCH; c++) {
        if (c < NKCH - 1) CP_WAIT1(); else CP_WAIT0();
        __syncthreads();
        if (c + 2 < NKCH) prefetch_tiles(sb, (c + 2) % 3, c + 2, tid, Ag, Bg);

        uint32_t Ab = sb + SM_A(c % 3);
        uint32_t Bb = sb + SM_B(c % 3);

        #pragma unroll
        for (int ks = 0; ks < 4; ks++) {
            uint32_t a[2][4];
            #pragma unroll
            for (int mi = 0; mi < 2; mi++) {
                int row = arow + mi * 16;
                int ch = (ks * 2 + ak) ^ (row & 7);
                LDSM_X4(a[mi][0], a[mi][1], a[mi][2], a[mi][3], Ab + row * 128 + (ch << 4));
            }
            uint32_t bf[8][2];
            #pragma unroll
            for (int nj = 0; nj < 4; nj++) {
                int row = brow + nj * 16;
                int ch = (ks * 2 + bk) ^ (row & 7);
                LDSM_X4(bf[2 * nj][0], bf[2 * nj][1], bf[2 * nj + 1][0], bf[2 * nj + 1][1],
                        Bb + row * 128 + (ch << 4));
            }
            #pragma unroll
            for (int mi = 0; mi < 2; mi++)
                #pragma unroll
                for (int nj = 0; nj < 8; nj++)
                    MMA16816(acc[mi][nj], a[mi], bf[nj][0], bf[nj][1]);
        }
    }

    // epilogue: direct float2 stores
    int om0 = omt * 128 + wr * 32 + (lane >> 2);
    int t0g = tt * 128 + wc * 64 + (lane & 3) * 2;
    #pragma unroll
    for (int mi = 0; mi < 2; mi++) {
        #pragma unroll
        for (int nj = 0; nj < 8; nj++) {
            float* p0 = out + ((size_t)b * OM + om0 + mi * 16) * NT + t0g + nj * 8;
            *(float2*)p0 = make_float2(acc[mi][nj][0], acc[mi][nj][1]);
            *(float2*)(p0 + 8 * NT) = make_float2(acc[mi][nj][2], acc[mi][nj][3]);
        }
    }
}

extern "C" void kernel_launch(void* const* d_in, const int* in_sizes, int n_in,
                              void* d_out, int out_size) {
    const float* x     = (const float*)d_in[0];   // (64,32,24,512)
    const float* adj   = (const float*)d_in[1];   // (24,24)
    const float* Theta = (const float*)d_in[2];   // (3,32,32)
    float* out = (float*)d_out;                   // (64,32,24,512)

    cudaFuncSetAttribute(cheb_gemm, cudaFuncAttributeMaxDynamicSharedMemorySize, SMEM_TOTAL);

    cheb_prep_all<<<NPREPW_BLK + NXCONV_BLK, 256>>>(x, adj, Theta);
    cheb_gemm<<<dim3(NT / 128, OM / 128, NB), 256, SMEM_TOTAL>>>(out);
}